// round 12
// baseline (speedup 1.0000x reference)
#include <cuda_runtime.h>

// SSIM loss: depthwise 11x11 gaussian (separable) + pointwise SSIM + global mean.
// B=16, C=3, H=W=512. Planes = 48. Tile 32x32 per block, halo 5 each side.
//
// Round 12: broadcast-shared P2 windows. Lanes l and l+16 of each P2 warp read
// IDENTICAL smem addresses (smem broadcast -> 1 wavefront per LDS.64 instead of 2);
// lower half blurs raw (t,i), upper half blurs (t^2+i^2, t*i) formed from the
// same loaded value (2 FSELs, no divergence, no extra regs). P2 load wavefronts
// ~331 -> ~170. P3 shuffle-exchange + occ 6 from R11 unchanged.

typedef unsigned long long u64;

#define TW 32
#define TH 32
#define HALO 5
#define SH 42
#define SW 42
#define IMG 512
#define NPLANES 48

#define RS 90            // (t,i) pair-plane row stride (floats): 13*row bank-pairs distinct
#define PP 3780          // SH * RS
#define CS 84            // sHT column stride (floats): quad 5*col mod 8 distinct -> LDS.128 conflict-free
#define PT 2688          // 32 * CS, per-pair sHT plane

#define OFF_HT PP
#define OFF_RED (OFF_HT + 2 * PT)
#define SMEM_FLOATS (OFF_RED + 8)
#define SMEM_BYTES (SMEM_FLOATS * 4)   // 36656 B -> 6 blocks/SM

__device__ constexpr float GW[11] = {
    0.00102838f, 0.00759877f, 0.03600077f, 0.10936079f, 0.21300554f,
    0.26601173f,
    0.21300554f, 0.10936079f, 0.03600077f, 0.00759877f, 0.00102838f};

#define SSIM_C1 0.0001f
#define SSIM_C2 0.0009f
#define INV_N (1.0f / (16.0f * 3.0f * 512.0f * 512.0f))

__device__ __forceinline__ u64 pack2(float lo, float hi) {
    u64 r;
    asm("mov.b64 %0, {%1, %2};" : "=l"(r) : "f"(lo), "f"(hi));
    return r;
}
__device__ __forceinline__ void unpack2(u64 v, float& lo, float& hi) {
    asm("mov.b64 {%0, %1}, %2;" : "=f"(lo), "=f"(hi) : "l"(v));
}
__device__ __forceinline__ u64 ffma2(u64 a, u64 b, u64 c) {
    u64 d;
    asm("fma.rn.f32x2 %0, %1, %2, %3;" : "=l"(d) : "l"(a), "l"(b), "l"(c));
    return d;
}
__device__ __forceinline__ u64 bcast2(float g) {
    unsigned u = __float_as_uint(g);
    return ((u64)u << 32) | (u64)u;
}

// Streaming vertical blur: 8 outputs from 18 consecutive row values of one column.
__device__ __forceinline__ void v_blur8(const float* __restrict__ base, u64 (&acc)[8]) {
#pragma unroll
    for (int r = 0; r < 8; r++) acc[r] = 0ull;
#pragma unroll
    for (int q = 0; q < 9; q++) {
        ulonglong2 vv = *(const ulonglong2*)(base + q * 4);
#pragma unroll
        for (int e = 0; e < 2; e++) {
            const int j = 2 * q + e;
            u64 v = e ? vv.y : vv.x;
#pragma unroll
            for (int r = 0; r < 8; r++) {
                if (j - r >= 0 && j - r < 11) acc[r] = ffma2(v, bcast2(GW[j - r]), acc[r]);
            }
        }
    }
}

__global__ void zero_out_kernel(float* out) { out[0] = 0.0f; }

__global__ __launch_bounds__(256, 6)
void ssim_kernel(const float* __restrict__ input, const float* __restrict__ target,
                 float* __restrict__ out) {
    extern __shared__ float smem[];
    float* sHT = smem + OFF_HT;
    float* red = smem + OFF_RED;

    const int tid = threadIdx.x;
    const int plane = blockIdx.z;
    const float* Tp = target + (size_t)plane * (IMG * IMG);
    const float* Ip = input + (size_t)plane * (IMG * IMG);
    const int gx0 = blockIdx.x * TW - HALO;
    const int gy0 = blockIdx.y * TH - HALO;

    // ---- Phase 1: load tile (+halo), store interleaved (t,i) pairs ----
    for (int idx = tid; idx < SH * SW; idx += 256) {
        int r = idx / SW;
        int c = idx - r * SW;
        int gx = gx0 + c;
        int gy = gy0 + r;
        float t = 0.0f, v = 0.0f;
        if ((unsigned)gx < (unsigned)IMG && (unsigned)gy < (unsigned)IMG) {
            t = Tp[gy * IMG + gx];
            v = Ip[gy * IMG + gx];
        }
        *(u64*)(smem + r * RS + c * 2) = pack2(t, v);
    }
    __syncthreads();

    // ---- Phase 2: horizontal blur with broadcast-shared windows.
    // Half-warp pairing: lanes l and l+16 read the SAME (row, chunk) window.
    //   half = lane>>4: 0 -> accumulate raw (t,i);  1 -> accumulate (t^2+i^2, t*i).
    // Warps 0-5: chunk = w>>1, row = (w&1)*16 + sl  (warp-uniform chunk).
    // Warps 6-7: tail slots s = (w-6)*16 + sl < 30: chunk = s/10, row = 32 + s%10.
    {
        const int w = tid >> 5;
        const int lane = tid & 31;
        const int half = lane >> 4;
        const int sl = lane & 15;
        int chunk, row;
        bool active = true;
        if (w < 6) {
            chunk = w >> 1;
            row = (w & 1) * 16 + sl;
        } else {
            int s = (w - 6) * 16 + sl;
            active = (s < 30);
            chunk = s / 10;
            row = 32 + s - chunk * 10;
        }
        if (active) {
            const int c0 = (chunk == 2) ? 21 : chunk * 11;
            const float* rowBase = smem + row * RS + c0 * 2;
            u64 acc[11];
#pragma unroll
            for (int r = 0; r < 11; r++) acc[r] = 0ull;
#pragma unroll
            for (int j = 0; j < 21; j++) {
                u64 v = *(const u64*)(rowBase + j * 2);   // identical addr in both halves
                float t, i;
                unpack2(v, t, i);
                float a = half ? fmaf(t, t, i * i) : t;
                float b = half ? (t * i) : i;
                u64 val = pack2(a, b);
#pragma unroll
                for (int r = 0; r < 11; r++) {
                    if (j - r >= 0 && j - r < 11) acc[r] = ffma2(val, bcast2(GW[j - r]), acc[r]);
                }
            }
            float* dst = sHT + half * PT + row * 2;
#pragma unroll
            for (int r = 0; r < 11; r++) *(u64*)(dst + (c0 + r) * CS) = acc[r];
        }
    }
    __syncthreads();

    // ---- Phase 3: vertical blur + shuffle exchange + SSIM (R11 structure).
    // Warp w: col group = w&1 (16 cols), row group tg = w>>1.
    // Lanes 0-15: pair 0; lanes 16-31: pair 1; same columns.
    {
        const int w = tid >> 5;
        const int lane = tid & 31;
        const int tx = lane & 15;
        const int half = lane >> 4;
        const int col = (w & 1) * 16 + tx;
        const int tg = w >> 1;            // output rows [8*tg, 8*tg+8)

        u64 res[8];
        v_blur8(sHT + half * PT + col * CS + tg * 16, res);

        float acc = 0.0f;
#pragma unroll
        for (int k = 0; k < 4; k++) {
            // half 0 handles rows k (needs partner's pair-1 stats);
            // half 1 handles rows k+4 (needs partner's pair-0 stats).
            u64 send = half ? res[k] : res[k + 4];
            u64 recv = __shfl_xor_sync(0xFFFFFFFFu, send, 16);
            u64 muv = half ? recv : res[k];        // (mu1, mu2)
            u64 prv = half ? res[k + 4] : recv;    // (Eq, E12)

            float mu1, mu2, eq, e12;
            unpack2(muv, mu1, mu2);
            unpack2(prv, eq, e12);
            float mu1s = mu1 * mu1;
            float mu2s = mu2 * mu2;
            float mu12 = mu1 * mu2;
            float musum = mu1s + mu2s;
            float ssum = eq - musum;   // sigma1^2 + sigma2^2
            float s12 = e12 - mu12;
            float num = (2.0f * mu12 + SSIM_C1) * (2.0f * s12 + SSIM_C2);
            float den = (musum + SSIM_C1) * (ssum + SSIM_C2);
            float ssim = __fdividef(num, den);

            int row = tg * 8 + k + half * 4;
            u64 tv = *(const u64*)(smem + (HALO + row) * RS + (HALO + col) * 2);
            float tc, ic;
            unpack2(tv, tc, ic);
            acc += (tc > 0.0f) ? (1.0f - ssim) : 0.0f;
        }

#pragma unroll
        for (int off = 16; off; off >>= 1) acc += __shfl_xor_sync(0xFFFFFFFFu, acc, off);
        if (lane == 0) red[w] = acc;
    }
    __syncthreads();
    if (tid == 0) {
        float s = 0.0f;
#pragma unroll
        for (int w = 0; w < 8; w++) s += red[w];
        atomicAdd(out, s * INV_N);
    }
}

extern "C" void kernel_launch(void* const* d_in, const int* in_sizes, int n_in,
                              void* d_out, int out_size) {
    const float* input = (const float*)d_in[0];
    const float* target = (const float*)d_in[1];
    float* out = (float*)d_out;

    cudaFuncSetAttribute(ssim_kernel, cudaFuncAttributeMaxDynamicSharedMemorySize, SMEM_BYTES);

    zero_out_kernel<<<1, 1>>>(out);
    dim3 grid(IMG / TW, IMG / TH, NPLANES);
    ssim_kernel<<<grid, 256, SMEM_BYTES>>>(input, target, out);
}

// round 13
// speedup vs baseline: 1.0209x; 1.0209x over previous
#include <cuda_runtime.h>
#include <cuda_fp16.h>

// SSIM loss: depthwise 11x11 gaussian (separable) + pointwise SSIM + global mean.
// B=16, C=3, H=W=512. Planes = 48. Tile 32x32 per block, halo 5 each side.
//
// Round 13: R11 structure (occ-6, split-pair P2, shuffle-exchange P3) with the
// horizontal-blur intermediate stored as f16x2 instead of f32x2. Halves P2-store
// and P3-load smem bytes (the binding L1 resource). Accumulation stays f32;
// only the h-blur result is rounded to fp16 (values in [0,2], rel ~5e-4; final
// scalar mean absorbs the noise). Smem 36.7KB -> 25.8KB.

typedef unsigned long long u64;
typedef unsigned int u32;

#define TW 32
#define TH 32
#define HALO 5
#define SH 42
#define SW 42
#define IMG 512
#define NPLANES 48

#define RS 90            // (t,i) f32 pair-plane row stride (floats): LDS.64 conflict-free
#define PP 3780          // SH * RS
#define CSH 44           // sHT column stride in u32 (42 rows + 2 pad): quad 3*col mod 8 distinct -> LDS.128 conflict-free
#define PT16 1408        // 32 * CSH, per-pair sHT plane (u32)

#define OFF_RED (PP + 2 * PT16)
#define SMEM_FLOATS (OFF_RED + 8)
#define SMEM_BYTES (SMEM_FLOATS * 4)   // 25840 B -> 6+ blocks/SM (reg-capped at 6)

__device__ constexpr float GW[11] = {
    0.00102838f, 0.00759877f, 0.03600077f, 0.10936079f, 0.21300554f,
    0.26601173f,
    0.21300554f, 0.10936079f, 0.03600077f, 0.00759877f, 0.00102838f};

#define SSIM_C1 0.0001f
#define SSIM_C2 0.0009f
#define INV_N (1.0f / (16.0f * 3.0f * 512.0f * 512.0f))

__device__ __forceinline__ u64 pack2(float lo, float hi) {
    u64 r;
    asm("mov.b64 %0, {%1, %2};" : "=l"(r) : "f"(lo), "f"(hi));
    return r;
}
__device__ __forceinline__ void unpack2(u64 v, float& lo, float& hi) {
    asm("mov.b64 {%0, %1}, %2;" : "=f"(lo), "=f"(hi) : "l"(v));
}
__device__ __forceinline__ u64 ffma2(u64 a, u64 b, u64 c) {
    u64 d;
    asm("fma.rn.f32x2 %0, %1, %2, %3;" : "=l"(d) : "l"(a), "l"(b), "l"(c));
    return d;
}
__device__ __forceinline__ u64 bcast2(float g) {
    unsigned u = __float_as_uint(g);
    return ((u64)u << 32) | (u64)u;
}
// f32x2 (u64) -> f16x2 (u32), round-to-nearest
__device__ __forceinline__ u32 f32x2_to_h2(u64 v) {
    float lo, hi;
    unpack2(v, lo, hi);
    u32 h;
    asm("cvt.rn.f16x2.f32 %0, %1, %2;" : "=r"(h) : "f"(hi), "f"(lo));  // h1=hi, h0=lo
    return h;
}
// f16x2 (u32) -> f32x2 (u64)
__device__ __forceinline__ u64 h2_to_f32x2(u32 h) {
    __half2 hv = *reinterpret_cast<__half2*>(&h);
    float2 f = __half22float2(hv);   // x = h0 (lo), y = h1 (hi)
    return pack2(f.x, f.y);
}

// Horizontal sliding blur of 11 output cols starting at c0 of one row; f16x2 out.
template <bool IS_PROD>
__device__ __forceinline__ void h_blur_task(const float* __restrict__ rowBase,
                                            u32* __restrict__ dstBase, int c0, int row) {
    u64 acc[11];
#pragma unroll
    for (int r = 0; r < 11; r++) acc[r] = 0ull;
#pragma unroll
    for (int j = 0; j < 21; j++) {
        u64 v;
        if (IS_PROD) {
            float2 ti = *(const float2*)(rowBase + (c0 + j) * 2);
            v = pack2(fmaf(ti.x, ti.x, ti.y * ti.y), ti.x * ti.y);
        } else {
            v = *(const u64*)(rowBase + (c0 + j) * 2);
        }
#pragma unroll
        for (int r = 0; r < 11; r++) {
            if (j - r >= 0 && j - r < 11) acc[r] = ffma2(v, bcast2(GW[j - r]), acc[r]);
        }
    }
#pragma unroll
    for (int r = 0; r < 11; r++) dstBase[(c0 + r) * CSH + row] = f32x2_to_h2(acc[r]);
}

// Streaming vertical blur over f16x2 column data: 8 outputs from rows [0,18) of
// one column. Loads 4 aligned uint4 (rows 0-19; rows 18,19 are ignored/padding).
__device__ __forceinline__ void v_blur8_h2(const u32* __restrict__ base, u64 (&acc)[8]) {
#pragma unroll
    for (int r = 0; r < 8; r++) acc[r] = 0ull;
#pragma unroll
    for (int q = 0; q < 4; q++) {
        uint4 w = ((const uint4*)base)[q];
        u32 hv[4] = {w.x, w.y, w.z, w.w};
#pragma unroll
        for (int e = 0; e < 4; e++) {
            const int j = 4 * q + e;
            if (j < 18) {
                u64 v = h2_to_f32x2(hv[e]);
#pragma unroll
                for (int r = 0; r < 8; r++) {
                    if (j - r >= 0 && j - r < 11) acc[r] = ffma2(v, bcast2(GW[j - r]), acc[r]);
                }
            }
        }
    }
    {
        uint2 w = ((const uint2*)base)[8];  // rows 16,17
#pragma unroll
        for (int e = 0; e < 2; e++) {
            const int j = 16 + e;
            u64 v = h2_to_f32x2(e ? w.y : w.x);
#pragma unroll
            for (int r = 0; r < 8; r++) {
                if (j - r < 11) acc[r] = ffma2(v, bcast2(GW[j - r]), acc[r]);
            }
        }
    }
}

__global__ void zero_out_kernel(float* out) { out[0] = 0.0f; }

__global__ __launch_bounds__(256, 6)
void ssim_kernel(const float* __restrict__ input, const float* __restrict__ target,
                 float* __restrict__ out) {
    extern __shared__ float smem[];
    u32* sHT = (u32*)(smem + PP);
    float* red = smem + OFF_RED;

    const int tid = threadIdx.x;
    const int plane = blockIdx.z;
    const float* Tp = target + (size_t)plane * (IMG * IMG);
    const float* Ip = input + (size_t)plane * (IMG * IMG);
    const int gx0 = blockIdx.x * TW - HALO;
    const int gy0 = blockIdx.y * TH - HALO;

    // ---- Phase 1: load tile (+halo), store interleaved (t,i) f32 pairs ----
    for (int idx = tid; idx < SH * SW; idx += 256) {
        int r = idx / SW;
        int c = idx - r * SW;
        int gx = gx0 + c;
        int gy = gy0 + r;
        float t = 0.0f, v = 0.0f;
        if ((unsigned)gx < (unsigned)IMG && (unsigned)gy < (unsigned)IMG) {
            t = Tp[gy * IMG + gx];
            v = Ip[gy * IMG + gx];
        }
        *(u64*)(smem + r * RS + c * 2) = pack2(t, v);
    }
    __syncthreads();

    // ---- Phase 2: split-pair horizontal blur, warp-uniform tasks (R11 map) ----
    {
        const int w = tid >> 5;
        const int lane = tid & 31;
        int pair, c0, row;
        bool active;
        if (w < 6) {
            pair = (w >= 3) ? 1 : 0;
            int cw = w - 3 * pair;
            c0 = (cw == 2) ? 21 : cw * 11;
            row = lane;
            active = true;
        } else {
            pair = w - 6;
            int seg = (lane >= 20) ? 2 : (lane >= 10 ? 1 : 0);
            c0 = (seg == 2) ? 21 : seg * 11;
            row = 32 + lane - seg * 10;
            active = (lane < 30);
        }
        if (active) {
            const float* rowBase = smem + row * RS;
            if (pair == 0)
                h_blur_task<false>(rowBase, sHT, c0, row);
            else
                h_blur_task<true>(rowBase, sHT + PT16, c0, row);
        }
    }
    __syncthreads();

    // ---- Phase 3: vertical blur + shuffle exchange + SSIM (R11 structure).
    // Warp w: col group = w&1 (16 cols), row group tg = w>>1.
    // Lanes 0-15: pair 0; lanes 16-31: pair 1; same columns.
    {
        const int w = tid >> 5;
        const int lane = tid & 31;
        const int tx = lane & 15;
        const int half = lane >> 4;
        const int col = (w & 1) * 16 + tx;
        const int tg = w >> 1;            // output rows [8*tg, 8*tg+8)

        u64 res[8];
        v_blur8_h2(sHT + half * PT16 + col * CSH + tg * 8, res);

        float acc = 0.0f;
#pragma unroll
        for (int k = 0; k < 4; k++) {
            u64 send = half ? res[k] : res[k + 4];
            u64 recv = __shfl_xor_sync(0xFFFFFFFFu, send, 16);
            u64 muv = half ? recv : res[k];        // (mu1, mu2)
            u64 prv = half ? res[k + 4] : recv;    // (Eq, E12)

            float mu1, mu2, eq, e12;
            unpack2(muv, mu1, mu2);
            unpack2(prv, eq, e12);
            float mu1s = mu1 * mu1;
            float mu2s = mu2 * mu2;
            float mu12 = mu1 * mu2;
            float musum = mu1s + mu2s;
            float ssum = eq - musum;   // sigma1^2 + sigma2^2
            float s12 = e12 - mu12;
            float num = (2.0f * mu12 + SSIM_C1) * (2.0f * s12 + SSIM_C2);
            float den = (musum + SSIM_C1) * (ssum + SSIM_C2);
            float ssim = __fdividef(num, den);

            int row = tg * 8 + k + half * 4;
            u64 tv = *(const u64*)(smem + (HALO + row) * RS + (HALO + col) * 2);
            float tc, ic;
            unpack2(tv, tc, ic);
            acc += (tc > 0.0f) ? (1.0f - ssim) : 0.0f;
        }

#pragma unroll
        for (int off = 16; off; off >>= 1) acc += __shfl_xor_sync(0xFFFFFFFFu, acc, off);
        if (lane == 0) red[w] = acc;
    }
    __syncthreads();
    if (tid == 0) {
        float s = 0.0f;
#pragma unroll
        for (int w = 0; w < 8; w++) s += red[w];
        atomicAdd(out, s * INV_N);
    }
}

extern "C" void kernel_launch(void* const* d_in, const int* in_sizes, int n_in,
                              void* d_out, int out_size) {
    const float* input = (const float*)d_in[0];
    const float* target = (const float*)d_in[1];
    float* out = (float*)d_out;

    cudaFuncSetAttribute(ssim_kernel, cudaFuncAttributeMaxDynamicSharedMemorySize, SMEM_BYTES);

    zero_out_kernel<<<1, 1>>>(out);
    dim3 grid(IMG / TW, IMG / TH, NPLANES);
    ssim_kernel<<<grid, 256, SMEM_BYTES>>>(input, target, out);
}